// round 15
// baseline (speedup 1.0000x reference)
#include <cuda_runtime.h>
#include <cstdint>

#define BATCH 512
#define TLEN  8192
#define DTC   1e-3f
#define NWARP 8
#define NTHR  (NWARP * 32)     // 256
#define LS    2                // steps per lane
#define TILE  (NTHR * LS)      // 512
#define NTILE (TLEN / TILE)    // 16
#define SEGW  8                // scan segment width (lanes)
#define NSEG  (NTHR / SEGW)    // 32 segments per block

// self = self ∘ prev (prev applied first)
__device__ __forceinline__ void compose(float& M00, float& M01, float& M10, float& M11,
                                        float& v0, float& v1,
                                        float pM00, float pM01, float pM10, float pM11,
                                        float pv0, float pv1) {
    float n00 = M00 * pM00 + M01 * pM10;
    float n01 = M00 * pM01 + M01 * pM11;
    float n10 = M10 * pM00 + M11 * pM10;
    float n11 = M10 * pM01 + M11 * pM11;
    float nv0 = M00 * pv0 + M01 * pv1 + v0;
    float nv1 = M10 * pv0 + M11 * pv1 + v1;
    M00 = n00; M01 = n01; M10 = n10; M11 = n11; v0 = nv0; v1 = nv1;
}

// T = I + dtA - q*(dtC);  b = q*d
__device__ __forceinline__ void step_transform(float4 q, float dx, float dy_,
                                               float dta00, float dta01, float dta10, float dta11,
                                               float dtc00, float dtc01, float dtc10, float dtc11,
                                               float& T00, float& T01, float& T10, float& T11,
                                               float& b0, float& b1) {
    T00 = 1.0f + dta00 - (q.x * dtc00 + q.y * dtc10);
    T01 =        dta01 - (q.x * dtc01 + q.y * dtc11);
    T10 =        dta10 - (q.z * dtc00 + q.w * dtc10);
    T11 = 1.0f + dta11 - (q.z * dtc01 + q.w * dtc11);
    b0  = q.x * dx + q.y * dy_;
    b1  = q.z * dx + q.w * dy_;
}

// ---------------- R11 data path + redundant block scan, 1 barrier/tile ----------------
__global__ __launch_bounds__(NTHR, 4)
void kFused(const float4* __restrict__ xic, const float4* __restrict__ dyv4,
            const float* __restrict__ Ac, const float* __restrict__ Cm,
            float4* __restrict__ out4) {
    __shared__ float4 wcM[2][NSEG];   // segment composite matrices (parity buffered)
    __shared__ float2 wcv[2][NSEG];   // segment composite offsets

    const int tid  = threadIdx.x;
    const int lane = tid & 31;
    const int seg  = tid >> 3;        // 8-lane segment index (0..31)
    const int sl   = tid & 7;         // lane within segment
    const int b    = blockIdx.x;

    const float dtc00 = DTC * __ldg(Cm + 0), dtc01 = DTC * __ldg(Cm + 1);
    const float dtc10 = DTC * __ldg(Cm + 2), dtc11 = DTC * __ldg(Cm + 3);
    const float dta00 = DTC * __ldg(Ac + 0), dta01 = DTC * __ldg(Ac + 1);
    const float dta10 = DTC * __ldg(Ac + 2), dta11 = DTC * __ldg(Ac + 3);

    // carry: maintained redundantly in EVERY warp's registers (identical values)
    float cx0 = 1.0f, cx1 = 0.0f;

    const size_t rowbase = (size_t)b * TLEN;
    const int s0 = tid * LS;                      // this thread's first step within a tile

    const float4* xp = xic  + rowbase + s0;
    const float4* dp = dyv4 + ((rowbase + s0) >> 1);
    float4*       op = out4 + ((rowbase + s0) >> 1);

    // prologue: load tile 0
    float4 q0  = __ldcs(xp);
    float4 q1  = __ldcs(xp + 1);
    float4 d01 = __ldcs(dp);                      // (d0.x, d0.y, d1.x, d1.y)

    for (int tile = 0; tile < NTILE; tile++) {
        const int p = tile & 1;

        // --- transforms for this tile (consume q0,q1,d01; kept for replay) ---
        float T00, T01, T10, T11, B00, B01;       // step 0
        float U00, U01, U10, U11, B10, B11;       // step 1
        step_transform(q0, d01.x, d01.y, dta00, dta01, dta10, dta11,
                       dtc00, dtc01, dtc10, dtc11, T00, T01, T10, T11, B00, B01);
        step_transform(q1, d01.z, d01.w, dta00, dta01, dta10, dta11,
                       dtc00, dtc01, dtc10, dtc11, U00, U01, U10, U11, B10, B11);

        // --- prefetch next tile into the now-dead registers ---
        if (tile + 1 < NTILE) {
            const float4* xn = xp + (tile + 1) * TILE;
            const float4* dn = dp + (tile + 1) * (TILE / 2);
            q0  = __ldcs(xn);
            q1  = __ldcs(xn + 1);
            d01 = __ldcs(dn);
        }

        // lane composite = U ∘ T
        float M00 = U00 * T00 + U01 * T10;
        float M01 = U00 * T01 + U01 * T11;
        float M10 = U10 * T00 + U11 * T10;
        float M11 = U10 * T01 + U11 * T11;
        float v0  = U00 * B00 + U01 * B01 + B10;
        float v1  = U10 * B00 + U11 * B01 + B11;

        // --- 8-wide segmented inclusive scan (3 rounds) ---
        #pragma unroll
        for (int d = 1; d < SEGW; d <<= 1) {
            float pM00 = __shfl_up_sync(0xffffffffu, M00, d, SEGW);
            float pM01 = __shfl_up_sync(0xffffffffu, M01, d, SEGW);
            float pM10 = __shfl_up_sync(0xffffffffu, M10, d, SEGW);
            float pM11 = __shfl_up_sync(0xffffffffu, M11, d, SEGW);
            float pv0  = __shfl_up_sync(0xffffffffu, v0,  d, SEGW);
            float pv1  = __shfl_up_sync(0xffffffffu, v1,  d, SEGW);
            if (sl >= d) compose(M00, M01, M10, M11, v0, v1, pM00, pM01, pM10, pM11, pv0, pv1);
        }

        if (sl == SEGW - 1) {
            wcM[p][seg] = make_float4(M00, M01, M10, M11);
            wcv[p][seg] = make_float2(v0, v1);
        }
        __syncthreads();   // the ONLY barrier per tile (wc publish)

        // --- redundant 32-wide block scan: EVERY warp scans all segment composites ---
        float4 Sm = wcM[p][lane];
        float2 Sv = wcv[p][lane];
        float S00 = Sm.x, S01 = Sm.y, S10 = Sm.z, S11 = Sm.w;
        float Sv0 = Sv.x, Sv1 = Sv.y;
        #pragma unroll
        for (int d = 1; d < 32; d <<= 1) {
            float pM00 = __shfl_up_sync(0xffffffffu, S00, d);
            float pM01 = __shfl_up_sync(0xffffffffu, S01, d);
            float pM10 = __shfl_up_sync(0xffffffffu, S10, d);
            float pM11 = __shfl_up_sync(0xffffffffu, S11, d);
            float pv0  = __shfl_up_sync(0xffffffffu, Sv0, d);
            float pv1  = __shfl_up_sync(0xffffffffu, Sv1, d);
            if (lane >= d) compose(S00, S01, S10, S11, Sv0, Sv1, pM00, pM01, pM10, pM11, pv0, pv1);
        }
        // segment-end states from register carry; shift down one for segment-start
        float se0 = S00 * cx0 + S01 * cx1 + Sv0;
        float se1 = S10 * cx0 + S11 * cx1 + Sv1;
        float sb0 = __shfl_up_sync(0xffffffffu, se0, 1);
        float sb1 = __shfl_up_sync(0xffffffffu, se1, 1);
        if (lane == 0) { sb0 = cx0; sb1 = cx1; }
        // next tile's carry (every warp computes the same value)
        cx0 = __shfl_sync(0xffffffffu, se0, 31);
        cx1 = __shfl_sync(0xffffffffu, se1, 31);
        // this thread's segment entry state, fetched from lane `seg` of its own warp
        float xg0 = __shfl_sync(0xffffffffu, sb0, seg);
        float xg1 = __shfl_sync(0xffffffffu, sb1, seg);

        // --- lane end state; lane start via shfl within segment ---
        float xe0 = M00 * xg0 + M01 * xg1 + v0;
        float xe1 = M10 * xg0 + M11 * xg1 + v1;
        float x0 = __shfl_up_sync(0xffffffffu, xe0, 1, SEGW);
        float x1 = __shfl_up_sync(0xffffffffu, xe1, 1, SEGW);
        if (sl == 0) { x0 = xg0; x1 = xg1; }

        // --- replay 2 steps from register transforms; one coalesced float4 store ---
        float4 o;
        o.x = dtc00 * x0 + dtc01 * x1;
        o.y = dtc10 * x0 + dtc11 * x1;
        {
            float nx0 = T00 * x0 + T01 * x1 + B00;
            float nx1 = T10 * x0 + T11 * x1 + B01;
            x0 = nx0; x1 = nx1;
        }
        o.z = dtc00 * x0 + dtc01 * x1;
        o.w = dtc10 * x0 + dtc11 * x1;

        __stcs(op + tile * (TILE / 2), o);
    }
}

extern "C" void kernel_launch(void* const* d_in, const int* in_sizes, int n_in,
                              void* d_out, int out_size) {
    const float4* xic  = (const float4*)d_in[0];  // [B,T,2,2] f32
    const float4* dyv4 = (const float4*)d_in[1];  // [B,T,2]   f32, float4 = 2 steps
    const float*  Ac   = (const float*)d_in[2];   // [2,2]
    const float*  Cm   = (const float*)d_in[3];   // [2,2]
    float4* out4 = (float4*)d_out;                // [B,T,2] viewed as float4 pairs

    kFused<<<BATCH, NTHR>>>(xic, dyv4, Ac, Cm, out4);
}

// round 16
// speedup vs baseline: 1.3743x; 1.3743x over previous
#include <cuda_runtime.h>
#include <cstdint>

#define BATCH 512
#define TLEN  8192
#define DTC   1e-3f
#define NWARP 8
#define NTHR  (NWARP * 32)     // 256
#define LS    2                // steps per lane
#define TILE  (NTHR * LS)      // 512
#define NTILE (TLEN / TILE)    // 16
#define SEGW  8                // scan segment width (lanes)
#define NSEG  (NTHR / SEGW)    // 32 segments per block

// self = self ∘ prev (prev applied first)
__device__ __forceinline__ void compose(float& M00, float& M01, float& M10, float& M11,
                                        float& v0, float& v1,
                                        float pM00, float pM01, float pM10, float pM11,
                                        float pv0, float pv1) {
    float n00 = M00 * pM00 + M01 * pM10;
    float n01 = M00 * pM01 + M01 * pM11;
    float n10 = M10 * pM00 + M11 * pM10;
    float n11 = M10 * pM01 + M11 * pM11;
    float nv0 = M00 * pv0 + M01 * pv1 + v0;
    float nv1 = M10 * pv0 + M11 * pv1 + v1;
    M00 = n00; M01 = n01; M10 = n10; M11 = n11; v0 = nv0; v1 = nv1;
}

// T = I + dtA - q*(dtC);  b = q*d
__device__ __forceinline__ void step_transform(float4 q, float dx, float dy_,
                                               float dta00, float dta01, float dta10, float dta11,
                                               float dtc00, float dtc01, float dtc10, float dtc11,
                                               float& T00, float& T01, float& T10, float& T11,
                                               float& b0, float& b1) {
    T00 = 1.0f + dta00 - (q.x * dtc00 + q.y * dtc10);
    T01 =        dta01 - (q.x * dtc01 + q.y * dtc11);
    T10 =        dta10 - (q.z * dtc00 + q.w * dtc10);
    T11 = 1.0f + dta11 - (q.z * dtc01 + q.w * dtc11);
    b0  = q.x * dx + q.y * dy_;
    b1  = q.z * dx + q.w * dy_;
}

// ---------------- R11 champion + packed wc + register carry ----------------
__global__ __launch_bounds__(NTHR, 4)
void kFused(const float4* __restrict__ xic, const float4* __restrict__ dyv4,
            const float* __restrict__ Ac, const float* __restrict__ Cm,
            float4* __restrict__ out4) {
    __shared__ float4 wcM[NSEG];     // segment composite matrices
    __shared__ float2 wcv[NSEG];     // segment composite offsets
    __shared__ float2 xs[NSEG];      // segment start states

    const int tid  = threadIdx.x;
    const int lane = tid & 31;
    const int w    = tid >> 5;
    const int seg  = tid >> 3;       // 8-lane segment index (0..31)
    const int sl   = tid & 7;        // lane within segment
    const int b    = blockIdx.x;

    const float dtc00 = DTC * __ldg(Cm + 0), dtc01 = DTC * __ldg(Cm + 1);
    const float dtc10 = DTC * __ldg(Cm + 2), dtc11 = DTC * __ldg(Cm + 3);
    const float dta00 = DTC * __ldg(Ac + 0), dta01 = DTC * __ldg(Ac + 1);
    const float dta10 = DTC * __ldg(Ac + 2), dta11 = DTC * __ldg(Ac + 3);

    // carry lives in warp-0 registers (identical across warp-0 lanes)
    float cx0 = 1.0f, cx1 = 0.0f;

    const size_t rowbase = (size_t)b * TLEN;
    const int s0 = tid * LS;                      // this thread's first step within a tile

    const float4* xp = xic  + rowbase + s0;
    const float4* dp = dyv4 + ((rowbase + s0) >> 1);
    float4*       op = out4 + ((rowbase + s0) >> 1);

    // prologue: load tile 0
    float4 q0  = __ldcs(xp);
    float4 q1  = __ldcs(xp + 1);
    float4 d01 = __ldcs(dp);                      // (d0.x, d0.y, d1.x, d1.y)

    for (int tile = 0; tile < NTILE; tile++) {
        // --- transforms for this tile (consume q0,q1,d01; kept for replay) ---
        float T00, T01, T10, T11, B00, B01;       // step 0
        float U00, U01, U10, U11, B10, B11;       // step 1
        step_transform(q0, d01.x, d01.y, dta00, dta01, dta10, dta11,
                       dtc00, dtc01, dtc10, dtc11, T00, T01, T10, T11, B00, B01);
        step_transform(q1, d01.z, d01.w, dta00, dta01, dta10, dta11,
                       dtc00, dtc01, dtc10, dtc11, U00, U01, U10, U11, B10, B11);

        // --- prefetch next tile into the now-dead registers ---
        if (tile + 1 < NTILE) {
            const float4* xn = xp + (tile + 1) * TILE;
            const float4* dn = dp + (tile + 1) * (TILE / 2);
            q0  = __ldcs(xn);
            q1  = __ldcs(xn + 1);
            d01 = __ldcs(dn);
        }

        // lane composite = U ∘ T
        float M00 = U00 * T00 + U01 * T10;
        float M01 = U00 * T01 + U01 * T11;
        float M10 = U10 * T00 + U11 * T10;
        float M11 = U10 * T01 + U11 * T11;
        float v0  = U00 * B00 + U01 * B01 + B10;
        float v1  = U10 * B00 + U11 * B01 + B11;

        // --- 8-wide segmented inclusive scan (3 rounds) ---
        #pragma unroll
        for (int d = 1; d < SEGW; d <<= 1) {
            float pM00 = __shfl_up_sync(0xffffffffu, M00, d, SEGW);
            float pM01 = __shfl_up_sync(0xffffffffu, M01, d, SEGW);
            float pM10 = __shfl_up_sync(0xffffffffu, M10, d, SEGW);
            float pM11 = __shfl_up_sync(0xffffffffu, M11, d, SEGW);
            float pv0  = __shfl_up_sync(0xffffffffu, v0,  d, SEGW);
            float pv1  = __shfl_up_sync(0xffffffffu, v1,  d, SEGW);
            if (sl >= d) compose(M00, M01, M10, M11, v0, v1, pM00, pM01, pM10, pM11, pv0, pv1);
        }

        if (sl == SEGW - 1) {
            wcM[seg] = make_float4(M00, M01, M10, M11);   // one STS.128
            wcv[seg] = make_float2(v0, v1);               // one STS.64
        }
        __syncthreads();   // sync A: wc ready

        // --- warp 0: scan the 32 segment composites, derive per-segment starts ---
        if (w == 0) {
            float4 Sm = wcM[lane];                        // one LDS.128
            float2 Sv = wcv[lane];                        // one LDS.64
            float S00 = Sm.x, S01 = Sm.y, S10 = Sm.z, S11 = Sm.w;
            float Sv0 = Sv.x, Sv1 = Sv.y;
            #pragma unroll
            for (int d = 1; d < 32; d <<= 1) {
                float pM00 = __shfl_up_sync(0xffffffffu, S00, d);
                float pM01 = __shfl_up_sync(0xffffffffu, S01, d);
                float pM10 = __shfl_up_sync(0xffffffffu, S10, d);
                float pM11 = __shfl_up_sync(0xffffffffu, S11, d);
                float pv0  = __shfl_up_sync(0xffffffffu, Sv0, d);
                float pv1  = __shfl_up_sync(0xffffffffu, Sv1, d);
                if (lane >= d) compose(S00, S01, S10, S11, Sv0, Sv1, pM00, pM01, pM10, pM11, pv0, pv1);
            }
            // segment-end states from register carry; shift down one for starts
            float xe0 = S00 * cx0 + S01 * cx1 + Sv0;
            float xe1 = S10 * cx0 + S11 * cx1 + Sv1;
            float xb0 = __shfl_up_sync(0xffffffffu, xe0, 1);
            float xb1 = __shfl_up_sync(0xffffffffu, xe1, 1);
            if (lane == 0) { xb0 = cx0; xb1 = cx1; }
            xs[lane] = make_float2(xb0, xb1);
            // next tile's carry stays in registers (lane-31 broadcast)
            cx0 = __shfl_sync(0xffffffffu, xe0, 31);
            cx1 = __shfl_sync(0xffffffffu, xe1, 31);
        }
        __syncthreads();   // sync B: xs ready

        // --- segment entry state; lane end state; lane start via 2-shfl ---
        float2 xg = xs[seg];
        float xe0 = M00 * xg.x + M01 * xg.y + v0;   // state at END of this lane's 2 steps
        float xe1 = M10 * xg.x + M11 * xg.y + v1;
        float x0 = __shfl_up_sync(0xffffffffu, xe0, 1, SEGW);
        float x1 = __shfl_up_sync(0xffffffffu, xe1, 1, SEGW);
        if (sl == 0) { x0 = xg.x; x1 = xg.y; }      // lane start state

        // --- replay 2 steps from register transforms; one coalesced float4 store ---
        float4 o;
        o.x = dtc00 * x0 + dtc01 * x1;
        o.y = dtc10 * x0 + dtc11 * x1;
        {
            float nx0 = T00 * x0 + T01 * x1 + B00;
            float nx1 = T10 * x0 + T11 * x1 + B01;
            x0 = nx0; x1 = nx1;
        }
        o.z = dtc00 * x0 + dtc01 * x1;
        o.w = dtc10 * x0 + dtc11 * x1;

        __stcs(op + tile * (TILE / 2), o);
    }
}

extern "C" void kernel_launch(void* const* d_in, const int* in_sizes, int n_in,
                              void* d_out, int out_size) {
    const float4* xic  = (const float4*)d_in[0];  // [B,T,2,2] f32
    const float4* dyv4 = (const float4*)d_in[1];  // [B,T,2]   f32, float4 = 2 steps
    const float*  Ac   = (const float*)d_in[2];   // [2,2]
    const float*  Cm   = (const float*)d_in[3];   // [2,2]
    float4* out4 = (float4*)d_out;                // [B,T,2] viewed as float4 pairs

    kFused<<<BATCH, NTHR>>>(xic, dyv4, Ac, Cm, out4);
}